// round 1
// baseline (speedup 1.0000x reference)
#include <cuda_runtime.h>
#include <cstdint>

#define BB 1024
#define LL 512
#define TT 50
#define START_TAG 48
#define STOP_TAG  49

// per-batch NLL scratch (static device global: allowed)
__device__ float g_nll[BB];

__device__ __forceinline__ unsigned long long pack2(float x, float y) {
    unsigned long long u;
    asm("mov.b64 %0, {%1,%2};" : "=l"(u) : "f"(x), "f"(y));
    return u;
}
__device__ __forceinline__ void unpack2(unsigned long long u, float &x, float &y) {
    asm("mov.b64 {%0,%1}, %2;" : "=f"(x), "=f"(y) : "l"(u));
}
// Blackwell packed f32x2 FMA: d = a*b + c on both 32-bit halves
__device__ __forceinline__ unsigned long long fma2(unsigned long long a,
                                                   unsigned long long b,
                                                   unsigned long long c) {
    unsigned long long d;
    asm("fma.rn.f32x2 %0, %1, %2, %3;" : "=l"(d) : "l"(a), "l"(b), "l"(c));
    return d;
}

// One warp per batch chain. 4 warps per CTA.
__global__ __launch_bounds__(128) void crf_fwd_kernel(
    const float* __restrict__ logits,   // [B, L, T]
    const float* __restrict__ trans,    // [T, T]
    const int*   __restrict__ labels,   // [B, L]
    const int*   __restrict__ lens)     // [B]
{
    // double-buffered duplicated s-vector per warp: [warp][buf][k] = {s[k], s[k]}
    __shared__ unsigned long long smem[4][2][64];

    const int wid = threadIdx.x >> 5;
    const int l   = threadIdx.x & 31;
    const int b   = blockIdx.x * 4 + wid;

    const bool hi = (l < (TT - 32));      // lane also owns j1 = l + 32 (l < 18)
    const int  j1 = l + 32;

    // ---- Precompute Texp columns for this lane's output rows (j0=l, j1=l+32).
    // exp(-10000) underflows to exactly 0 == semiring zero of -inf. 
    unsigned long long r[TT];
#pragma unroll
    for (int k = 0; k < TT; k++) {
        float a = __expf(trans[l * TT + k]);
        float c = hi ? __expf(trans[j1 * TT + k]) : 0.0f;
        r[k] = pack2(a, c);
    }
    // stop-row weights exp(trans[STOP][j])
    const float ts0 = __expf(trans[STOP_TAG * TT + l]);
    const float ts1 = hi ? __expf(trans[STOP_TAG * TT + j1]) : 0.0f;

    // ---- init s = exp(alpha0): 1 at START, 0 elsewhere
    float s0 = 0.0f;
    float s1 = (hi && j1 == START_TAG) ? 1.0f : 0.0f;
    smem[wid][0][l] = pack2(s0, s0);
    if (hi) smem[wid][0][j1] = pack2(s1, s1);
    __syncwarp();

    const int len = lens[b];
    const float* lg = logits + (size_t)b * (LL * TT);

    // prefetch step-0 logits
    float c0 = lg[l];
    float c1 = hi ? lg[j1] : 0.0f;

    int E = 0;  // exact power-of-2 exponent offset: alpha = log(s) + E*ln2

    for (int t = 0; t < len; t++) {
        // prefetch next step's logits (hide DRAM latency behind the matvec)
        float n0 = 0.0f, n1 = 0.0f;
        if (t + 1 < len) {
            const float* p = lg + (size_t)(t + 1) * TT;
            n0 = p[l];
            n1 = hi ? p[j1] : 0.0f;
        }

        // ---- matvec p[j] = sum_k Texp[j,k] * s[k]  (packed pairs, 2 acc chains)
        const ulonglong2* e2 = (const ulonglong2*)smem[wid][t & 1];
        unsigned long long a0 = 0ull, a1 = 0ull;
#pragma unroll
        for (int kk = 0; kk < 25; kk++) {
            ulonglong2 ee = e2[kk];                 // {s[2kk],s[2kk]},{s[2kk+1],s[2kk+1]}
            a0 = fma2(r[2 * kk],     ee.x, a0);
            a1 = fma2(r[2 * kk + 1], ee.y, a1);
        }
        float q0x, q0y, q1x, q1y;
        unpack2(a0, q0x, q0y);
        unpack2(a1, q1x, q1y);
        float p0 = q0x + q1x;   // p[j0]
        float p1 = q0y + q1y;   // p[j1]

        // ---- multiply by exp(logit), renormalize by exact power of two
        s0 = p0 * __expf(c0);
        s1 = hi ? (p1 * __expf(c1)) : 0.0f;

        float m = fmaxf(s0, s1);
#pragma unroll
        for (int o = 16; o; o >>= 1)
            m = fmaxf(m, __shfl_xor_sync(0xffffffffu, m, o));

        int e = (__float_as_int(m) >> 23) - 127;        // m > 0 always (see theory)
        float sc = __int_as_float((127 - e) << 23);     // 2^{-e}
        s0 *= sc;
        s1 *= sc;
        E += e;

        unsigned long long* wbuf = smem[wid][(t + 1) & 1];
        wbuf[l] = pack2(s0, s0);
        if (hi) wbuf[j1] = pack2(s1, s1);
        __syncwarp();

        c0 = n0;
        c1 = n1;
    }

    // ---- partition = log( sum_j s[j]*exp(trans[STOP][j]) ) + E*ln2
    float w = s0 * ts0 + s1 * ts1;
#pragma unroll
    for (int o = 16; o; o >>= 1)
        w += __shfl_xor_sync(0xffffffffu, w, o);
    float partition = logf(w) + (float)E * 0.69314718055994530942f;

    // ---- gold score: emission + label-path transitions
    const int* labs = labels + (size_t)b * LL;
    float gold = 0.0f;
    for (int t = l; t < len; t += 32) {
        int lab  = labs[t];
        int prev = (t == 0) ? START_TAG : labs[t - 1];
        gold += lg[(size_t)t * TT + lab];
        gold += trans[lab * TT + prev];
    }
#pragma unroll
    for (int o = 16; o; o >>= 1)
        gold += __shfl_xor_sync(0xffffffffu, gold, o);

    if (l == 0) {
        gold += trans[STOP_TAG * TT + labs[len - 1]];   // final transition to STOP
        g_nll[b] = partition - gold;
    }
}

__global__ void crf_reduce_kernel(float* __restrict__ out) {
    __shared__ float sh[256];
    float s = 0.0f;
    for (int i = threadIdx.x; i < BB; i += 256) s += g_nll[i];
    sh[threadIdx.x] = s;
    __syncthreads();
    for (int o = 128; o; o >>= 1) {
        if (threadIdx.x < o) sh[threadIdx.x] += sh[threadIdx.x + o];
        __syncthreads();
    }
    if (threadIdx.x == 0) out[0] = sh[0] / (float)BB;
}

extern "C" void kernel_launch(void* const* d_in, const int* in_sizes, int n_in,
                              void* d_out, int out_size) {
    const float* logits = (const float*)d_in[0];
    const float* trans  = (const float*)d_in[1];
    const int*   labels = (const int*)d_in[2];
    const int*   lens   = (const int*)d_in[3];

    crf_fwd_kernel<<<BB / 4, 128>>>(logits, trans, labels, lens);
    crf_reduce_kernel<<<1, 256>>>((float*)d_out);
}

// round 2
// speedup vs baseline: 1.7237x; 1.7237x over previous
#include <cuda_runtime.h>
#include <cstdint>

#define BB 1024
#define LL 512
#define TT 50
#define START_TAG 48
#define STOP_TAG  49

// per-batch NLL scratch
__device__ float g_nll[BB];

__device__ __forceinline__ unsigned long long pack2(float x, float y) {
    unsigned long long u;
    asm("mov.b64 %0, {%1,%2};" : "=l"(u) : "f"(x), "f"(y));
    return u;
}
__device__ __forceinline__ void unpack2(unsigned long long u, float &x, float &y) {
    asm("mov.b64 {%0,%1}, %2;" : "=f"(x), "=f"(y) : "l"(u));
}
// Blackwell packed f32x2 FMA: d = a*b + c on both 32-bit halves
__device__ __forceinline__ unsigned long long fma2(unsigned long long a,
                                                   unsigned long long b,
                                                   unsigned long long c) {
    unsigned long long d;
    asm("fma.rn.f32x2 %0, %1, %2, %3;" : "=l"(d) : "l"(a), "l"(b), "l"(c));
    return d;
}
// warp max of NON-NEGATIVE floats via single integer redux (bit pattern order == value order)
__device__ __forceinline__ float warp_max_pos(float x) {
    int xi = __float_as_int(x);
    int r;
    asm("redux.sync.max.s32 %0, %1, 0xffffffff;" : "=r"(r) : "r"(xi));
    return __int_as_float(r);
}

// One warp per batch chain. 4 warps per CTA.
__global__ __launch_bounds__(128) void crf_fwd_kernel(
    const float* __restrict__ logits,   // [B, L, T]
    const float* __restrict__ trans,    // [T, T]
    const int*   __restrict__ labels,   // [B, L]
    const int*   __restrict__ lens)     // [B]
{
    // double-buffered duplicated s-vector per warp: [warp][buf][k] = {s[k], s[k]}
    __shared__ unsigned long long smem[4][2][64];

    const int wid = threadIdx.x >> 5;
    const int l   = threadIdx.x & 31;
    const int b   = blockIdx.x * 4 + wid;

    const bool hi = (l < (TT - 32));      // lane also owns j1 = l + 32 (l < 18)
    const int  j1 = l + 32;

    // Texp columns for this lane's output rows (j0=l, j1=l+32); exp(-10000)->0 == semiring zero
    unsigned long long r[TT];
#pragma unroll
    for (int k = 0; k < TT; k++) {
        float a = __expf(trans[l * TT + k]);
        float c = hi ? __expf(trans[j1 * TT + k]) : 0.0f;
        r[k] = pack2(a, c);
    }
    const float ts0 = __expf(trans[STOP_TAG * TT + l]);
    const float ts1 = hi ? __expf(trans[STOP_TAG * TT + j1]) : 0.0f;

    // init s = exp(alpha0): 1 at START, 0 elsewhere
    float s0 = 0.0f;
    float s1 = (hi && j1 == START_TAG) ? 1.0f : 0.0f;
    smem[wid][0][l] = pack2(s0, s0);
    if (hi) smem[wid][0][j1] = pack2(s1, s1);
    __syncwarp();

    const int len = lens[b];
    const float* lg = logits + (size_t)b * (LL * TT);

    // logit prefetch ring, depth 3 (ring of 4, unroll-4 keeps indices constant)
    float pf0[4], pf1[4];
#pragma unroll
    for (int i = 0; i < 3; i++) {
        int idx = min(i, len - 1);
        pf0[i] = lg[(size_t)idx * TT + l];
        pf1[i] = hi ? lg[(size_t)idx * TT + j1] : 0.0f;
    }

    int E = 0;  // exact power-of-2 exponent offset: alpha = log(s) + E*ln2

#pragma unroll 4
    for (int t = 0; t < len; t++) {
        // refill prefetch slot (t+3)
        {
            int pidx = min(t + 3, len - 1);
            pf0[(t + 3) & 3] = lg[(size_t)pidx * TT + l];
            pf1[(t + 3) & 3] = hi ? lg[(size_t)pidx * TT + j1] : 0.0f;
        }

        // matvec p[j] = sum_k Texp[j,k] * s[k] : 4 independent packed chains
        const ulonglong2* e2 = (const ulonglong2*)smem[wid][t & 1];
        unsigned long long a0 = 0ull, a1 = 0ull, a2 = 0ull, a3 = 0ull;
#pragma unroll
        for (int kk = 0; kk < 25; kk++) {
            ulonglong2 ee = e2[kk];
            if (kk & 1) {
                a2 = fma2(r[2 * kk],     ee.x, a2);
                a3 = fma2(r[2 * kk + 1], ee.y, a3);
            } else {
                a0 = fma2(r[2 * kk],     ee.x, a0);
                a1 = fma2(r[2 * kk + 1], ee.y, a1);
            }
        }
        a0 = fma2(pack2(1.0f, 1.0f), a2, a0);   // combine chains (packed add via fma)
        a1 = fma2(pack2(1.0f, 1.0f), a3, a1);
        float q0x, q0y, q1x, q1y;
        unpack2(a0, q0x, q0y);
        unpack2(a1, q1x, q1y);
        float p0 = q0x + q1x;   // p[j0]
        float p1 = q0y + q1y;   // p[j1]

        // multiply by exp(logit)
        s0 = p0 * __expf(pf0[t & 3]);
        s1 = hi ? (p1 * __expf(pf1[t & 3])) : 0.0f;

        // exact power-of-2 renormalization every 4 steps (single-redux max; s >= 0)
        if ((t & 3) == 3) {
            float m = warp_max_pos(fmaxf(s0, s1));
            int e = (__float_as_int(m) >> 23) - 127;        // m > 0 always
            float sc = __int_as_float((127 - e) << 23);     // 2^{-e}
            s0 *= sc;
            s1 *= sc;
            E += e;
        }

        unsigned long long* wbuf = smem[wid][(t + 1) & 1];
        wbuf[l] = pack2(s0, s0);
        if (hi) wbuf[j1] = pack2(s1, s1);
        __syncwarp();
    }

    // partition = log( sum_j s[j]*exp(trans[STOP][j]) ) + E*ln2
    float w = s0 * ts0 + s1 * ts1;
#pragma unroll
    for (int o = 16; o; o >>= 1)
        w += __shfl_xor_sync(0xffffffffu, w, o);
    float partition = logf(w) + (float)E * 0.69314718055994530942f;

    // gold score: emission + label-path transitions
    const int* labs = labels + (size_t)b * LL;
    float gold = 0.0f;
    for (int t = l; t < len; t += 32) {
        int lab  = labs[t];
        int prev = (t == 0) ? START_TAG : labs[t - 1];
        gold += lg[(size_t)t * TT + lab];
        gold += trans[lab * TT + prev];
    }
#pragma unroll
    for (int o = 16; o; o >>= 1)
        gold += __shfl_xor_sync(0xffffffffu, gold, o);

    if (l == 0) {
        gold += trans[STOP_TAG * TT + labs[len - 1]];   // final transition to STOP
        g_nll[b] = partition - gold;
    }
}

__global__ __launch_bounds__(1024) void crf_reduce_kernel(float* __restrict__ out) {
    __shared__ float sh[32];
    int tid = threadIdx.x;
    float s = g_nll[tid];
#pragma unroll
    for (int o = 16; o; o >>= 1) s += __shfl_xor_sync(0xffffffffu, s, o);
    if ((tid & 31) == 0) sh[tid >> 5] = s;
    __syncthreads();
    if (tid < 32) {
        float v = sh[tid];
#pragma unroll
        for (int o = 16; o; o >>= 1) v += __shfl_xor_sync(0xffffffffu, v, o);
        if (tid == 0) out[0] = v / (float)BB;
    }
}

extern "C" void kernel_launch(void* const* d_in, const int* in_sizes, int n_in,
                              void* d_out, int out_size) {
    const float* logits = (const float*)d_in[0];
    const float* trans  = (const float*)d_in[1];
    const int*   labels = (const int*)d_in[2];
    const int*   lens   = (const int*)d_in[3];

    crf_fwd_kernel<<<BB / 4, 128>>>(logits, trans, labels, lens);
    crf_reduce_kernel<<<1, 1024>>>((float*)d_out);
}